// round 7
// baseline (speedup 1.0000x reference)
#include <cuda_runtime.h>

#define NBIN 256
#define EPSF 1e-10f
#define CHUNK_LG 12
#define CHUNK (1 << CHUNK_LG)          // 4096 elements per chunk
#define MAXN 67108864                  // 4*256^3
#define MAXCHUNK (MAXN / CHUNK)        // 16384

// ---------------- device scratch (static; no runtime allocation) ----------------
__device__ unsigned int g_min_ord;
__device__ unsigned int g_cnt0[256 * MAXCHUNK];   // [bin*nchunk + chunk]
__device__ unsigned int g_cnt1[256 * MAXCHUNK];
__device__ unsigned int g_bs0[NBIN + 1];          // global group starts (bins 0..255, +end)
__device__ unsigned int g_bs1[NBIN + 1];
__device__ float g_sorted0[MAXN];                 // d values, stably sorted by bin
__device__ float g_sorted1[MAXN];
__device__ float g_h0[NBIN];
__device__ float g_h1[NBIN];

// Order-preserving float<->uint so unsigned atomicMin == float min.
__device__ __forceinline__ unsigned int f2ord(float f) {
    unsigned int u = __float_as_uint(f);
    return (u & 0x80000000u) ? ~u : (u | 0x80000000u);
}
__device__ __forceinline__ float ord2f(unsigned int o) {
    return __uint_as_float((o & 0x80000000u) ? (o & 0x7FFFFFFFu) : ~o);
}

// ---------------- Cephes-style f32 log/exp (XLA:CPU / Eigen lineage, FMA form) ----
__device__ __forceinline__ float xla_logf(float x) {
    unsigned int ix = __float_as_uint(x);
    int e = (int)(ix >> 23) - 126;
    float m = __uint_as_float((ix & 0x007FFFFFu) | 0x3F000000u);   // [0.5, 1)
    float ef = (float)e;
    if (m < 0.707106781186547524f) { ef -= 1.0f; m = m + m; }      // exact
    float xm = m - 1.0f;                                           // exact (Sterbenz)
    float z = __fmul_rn(xm, xm);
    float y = 7.0376836292E-2f;
    y = __fmaf_rn(y, xm, -1.1514610310E-1f);
    y = __fmaf_rn(y, xm,  1.1676998740E-1f);
    y = __fmaf_rn(y, xm, -1.2420140846E-1f);
    y = __fmaf_rn(y, xm,  1.4249322787E-1f);
    y = __fmaf_rn(y, xm, -1.6668057665E-1f);
    y = __fmaf_rn(y, xm,  2.0000714765E-1f);
    y = __fmaf_rn(y, xm, -2.4999993993E-1f);
    y = __fmaf_rn(y, xm,  3.3333331174E-1f);
    y = __fmul_rn(y, xm);
    y = __fmul_rn(y, z);
    y = __fmaf_rn(ef, -2.12194440e-4f, y);
    y = __fmaf_rn(z, -0.5f, y);
    float r = __fadd_rn(xm, y);
    r = __fmaf_rn(ef, 0.693359375f, r);
    return r;
}
__device__ __forceinline__ float xla_expf(float x) {
    x = fminf(x, 88.723164f);
    x = fmaxf(x, -88.723164f);
    float m = floorf(__fmaf_rn(x, 1.44269504088896341f, 0.5f));
    float r = __fmaf_rn(m, -0.693359375f, x);
    r = __fmaf_rn(m, 2.12194440e-4f, r);
    float r2 = __fmul_rn(r, r);
    float p = 1.9875691500E-4f;
    p = __fmaf_rn(p, r, 1.3981999507E-3f);
    p = __fmaf_rn(p, r, 8.3334519073E-3f);
    p = __fmaf_rn(p, r, 4.1665795894E-2f);
    p = __fmaf_rn(p, r, 1.6666665459E-1f);
    p = __fmaf_rn(p, r, 5.0000001201E-1f);
    float y = __fmaf_rn(p, r2, r);
    y = __fadd_rn(y, 1.0f);
    int mi = (int)m;
    return __fmul_rn(y, __uint_as_float((unsigned int)(mi + 127) << 23));
}

// ---------------- shared binning math (bit-exact vs reference) ----------------
// dh = (0 - hmin)/255 ; x = (v - hmin)/dh ; idx = floor(x) ; d = x - idx
__device__ __forceinline__ void bin_of(float v, float hmin, float dh,
                                       bool& keep, int& idx, float& d) {
    keep = (v >= hmin) && (v <= 0.0f);
    float x  = __fdiv_rn(v - hmin, dh);
    float fi = floorf(x);
    idx = (int)fi;
    d   = x - fi;          // exact
}

// ---------------- kernel 0: reset counters + min ----------------
__global__ void k_init(int nchunk) {
    int total = 256 * nchunk;
    int stride = gridDim.x * blockDim.x;
    for (int i = blockIdx.x * blockDim.x + threadIdx.x; i < total; i += stride) {
        g_cnt0[i] = 0u;
        g_cnt1[i] = 0u;
    }
    if (blockIdx.x == 0 && threadIdx.x == 0) g_min_ord = 0xFFFFFFFFu;
}

// ---------------- kernel 1: global min of img0 (exact in any order) -----------
__global__ void k_min(const float* __restrict__ img, int n) {
    float m = 3.402823466e38f;
    int stride = gridDim.x * blockDim.x;
    for (int i = blockIdx.x * blockDim.x + threadIdx.x; i < n; i += stride)
        m = fminf(m, img[i]);
    #pragma unroll
    for (int o = 16; o; o >>= 1) m = fminf(m, __shfl_xor_sync(0xFFFFFFFFu, m, o));
    __shared__ float sm[32];
    int lane = threadIdx.x & 31, w = threadIdx.x >> 5;
    if (lane == 0) sm[w] = m;
    __syncthreads();
    if (w == 0) {
        int nw = (blockDim.x + 31) >> 5;
        m = (lane < nw) ? sm[lane] : 3.402823466e38f;
        #pragma unroll
        for (int o = 16; o; o >>= 1) m = fminf(m, __shfl_xor_sync(0xFFFFFFFFu, m, o));
        if (lane == 0) atomicMin(&g_min_ord, f2ord(m));
    }
}

// ---------------- kernel 2: per-(bin, chunk) counts ----------------
__global__ void k_count(const float* __restrict__ i0, const float* __restrict__ i1,
                        int n, int nchunk) {
    float hmin = ord2f(g_min_ord);
    float dh   = __fdiv_rn(0.0f - hmin, 255.0f);
    int stride = gridDim.x * blockDim.x;
    for (int i = blockIdx.x * blockDim.x + threadIdx.x; i < n; i += stride) {
        int chunk = i >> CHUNK_LG;
        bool keep; int idx; float d;
        bin_of(i0[i], hmin, dh, keep, idx, d);
        if (keep) atomicAdd(&g_cnt0[idx * nchunk + chunk], 1u);
        bin_of(i1[i], hmin, dh, keep, idx, d);
        if (keep) atomicAdd(&g_cnt1[idx * nchunk + chunk], 1u);
    }
}

// ---------------- kernel 3: scan counts -> global start offsets ----------------
// One block, 512 threads: thread = (img<<8)|bin.
__global__ void k_scan(int nchunk) {
    int img = threadIdx.x >> 8;
    int b   = threadIdx.x & 255;
    unsigned int* cnt = img ? g_cnt1 : g_cnt0;
    unsigned int* bs  = img ? g_bs1  : g_bs0;

    unsigned int tot = 0;
    for (int c = 0; c < nchunk; c++) tot += cnt[b * nchunk + c];

    __shared__ unsigned int s_tot[512];
    s_tot[threadIdx.x] = tot;
    __syncthreads();
    if (b == 0) {     // exclusive scan over this image's 256 bins
        unsigned int run = 0;
        for (int j = 0; j < 256; j++) {
            unsigned int v = s_tot[(img << 8) + j];
            s_tot[(img << 8) + j] = run;
            run += v;
        }
        bs[256] = run;
    }
    __syncthreads();
    unsigned int run = s_tot[threadIdx.x];
    bs[b] = run;
    for (int c = 0; c < nchunk; c++) {
        unsigned int v = cnt[b * nchunk + c];
        cnt[b * nchunk + c] = run;     // rewrite to global start for (bin, chunk)
        run += v;
    }
}

// ---------------- kernel 4: order-preserving placement (stable by element order)
// grid (nchunk, 2); block 256. Thread 0 serializes intra-chunk ranking.
__global__ void k_place(const float* __restrict__ i0, const float* __restrict__ i1,
                        int n, int nchunk) {
    __shared__ unsigned int s_start[256];
    __shared__ float s_d[256];
    __shared__ int s_idx[256];
    __shared__ unsigned char s_keep[256];
    __shared__ unsigned int s_slot[256];

    int img = blockIdx.y;
    const float* in = img ? i1 : i0;
    const unsigned int* cnt = img ? g_cnt1 : g_cnt0;
    float* outp = img ? g_sorted1 : g_sorted0;

    int chunk = blockIdx.x;
    int base  = chunk << CHUNK_LG;
    int t     = threadIdx.x;

    s_start[t] = cnt[t * nchunk + chunk];
    float hmin = ord2f(g_min_ord);
    float dh   = __fdiv_rn(0.0f - hmin, 255.0f);

    for (int w = 0; w < (CHUNK / 256); w++) {
        int i = base + (w << 8) + t;
        float v = (i < n) ? in[i] : 1.0f;
        bool keep; int idx; float d;
        bin_of(v, hmin, dh, keep, idx, d);
        if (i >= n) keep = false;
        s_d[t] = d; s_idx[t] = idx; s_keep[t] = keep ? 1 : 0;
        __syncthreads();
        if (t == 0) {
            #pragma unroll 4
            for (int j = 0; j < 256; j++)
                if (s_keep[j]) s_slot[j] = s_start[s_idx[j]]++;
        }
        __syncthreads();
        if (s_keep[t]) outp[s_slot[t]] = s_d[t];
        __syncthreads();
    }
}

// ---------------- kernel 5: exact sequential f32 fold per bin ----------------
// Reference order: scatter1 = all w0 = (1-d) in element order, then scatter2 =
// all w1 = d. For bin b: fold (1-d) over group b, then d over group b-1.
__global__ void k_fold() {
    int img = blockIdx.x;
    const float* sd = img ? g_sorted1 : g_sorted0;
    const unsigned int* bs = img ? g_bs1 : g_bs0;
    float* h = img ? g_h1 : g_h0;
    int b = threadIdx.x;

    float acc = 0.0f;
    unsigned int s = bs[b], e = bs[b + 1];
    for (unsigned int i = s; i < e; i++) {
        float w = __fsub_rn(1.0f, sd[i]);
        acc = __fadd_rn(acc, w);
    }
    if (b > 0) {
        unsigned int s2 = bs[b - 1], e2 = bs[b];
        for (unsigned int i = s2; i < e2; i++)
            acc = __fadd_rn(acc, sd[i]);
    }
    h[b] = acc;
}

// ---------------- kernel 6: finalize (single thread, reference op-order) -------
__global__ void k_final(float* __restrict__ out) {
    if (threadIdx.x != 0 || blockIdx.x != 0) return;

    float S0 = 0.0f, S1 = 0.0f;              // sequential folds, XLA reduce order
    for (int t = 0; t < NBIN; t++) S0 = __fadd_rn(S0, g_h0[t]);
    for (int t = 0; t < NBIN; t++) S1 = __fadd_rn(S1, g_h1[t]);

    float d0 = __fadd_rn(S0, EPSF);
    float d1 = __fadd_rn(S1, EPSF);

    float acc = 0.0f;
    for (int t = 0; t < NBIN; t++) {
        float h0n = __fdiv_rn(__fadd_rn(g_h0[t], EPSF), d0);
        float h1n = __fdiv_rn(__fadd_rn(g_h1[t], EPSF), d1);
        float num = __fadd_rn(h1n, EPSF);
        float qi  = __fdiv_rn(num, h1n);
        float qt  = __fdiv_rn(num, h0n);
        float inp = xla_logf(qi);
        float tgt = xla_logf(qt);
        float et  = xla_expf(tgt);
        float term = __fmul_rn(et, __fsub_rn(tgt, inp));
        acc = __fadd_rn(acc, term);
    }
    out[0] = __fdiv_rn(acc, 256.0f);
}

// ---------------- launch ----------------
extern "C" void kernel_launch(void* const* d_in, const int* in_sizes, int n_in,
                              void* d_out, int out_size) {
    const float* img0 = (const float*)d_in[0];
    const float* img1 = (const float*)d_in[1];
    float* out = (float*)d_out;
    int n = in_sizes[0];
    if (n > MAXN) n = MAXN;
    int nchunk = (n + CHUNK - 1) / CHUNK;

    const int BLOCKS = 1184;
    const int TPB    = 256;

    k_init <<<BLOCKS, TPB>>>(nchunk);
    k_min  <<<BLOCKS, TPB>>>(img0, n);
    k_count<<<BLOCKS, TPB>>>(img0, img1, n, nchunk);
    k_scan <<<1, 512>>>(nchunk);
    k_place<<<dim3(nchunk, 2), TPB>>>(img0, img1, n, nchunk);
    k_fold <<<2, NBIN>>>();
    k_final<<<1, 32>>>(out);
}

// round 8
// speedup vs baseline: 3.1975x; 3.1975x over previous
#include <cuda_runtime.h>

#define NBIN 256
#define EPSF 1e-10f
#define CHUNK_LG 12
#define CHUNK (1 << CHUNK_LG)          // 4096 elements per chunk
#define MAXN 67108864                  // 4*256^3
#define MAXCHUNK (MAXN / CHUNK)        // 16384
#define FT 4096                        // fold tile (floats)

// ---------------- device scratch (static; no runtime allocation) ----------------
__device__ unsigned int g_min_ord;
__device__ unsigned int g_cnt0[256 * MAXCHUNK];   // [bin*nchunk + chunk]
__device__ unsigned int g_cnt1[256 * MAXCHUNK];
__device__ unsigned int g_bs0[NBIN + 1];          // global group starts
__device__ unsigned int g_bs1[NBIN + 1];
__device__ float g_sorted0[MAXN];                 // d values, stably sorted by bin
__device__ float g_sorted1[MAXN];
__device__ float g_h0[NBIN];
__device__ float g_h1[NBIN];

// Order-preserving float<->uint so unsigned atomicMin == float min.
__device__ __forceinline__ unsigned int f2ord(float f) {
    unsigned int u = __float_as_uint(f);
    return (u & 0x80000000u) ? ~u : (u | 0x80000000u);
}
__device__ __forceinline__ float ord2f(unsigned int o) {
    return __uint_as_float((o & 0x80000000u) ? (o & 0x7FFFFFFFu) : ~o);
}

// ---------------- Cephes-style f32 log/exp (XLA:CPU lineage, FMA form) ----------
__device__ __forceinline__ float xla_logf(float x) {
    unsigned int ix = __float_as_uint(x);
    int e = (int)(ix >> 23) - 126;
    float m = __uint_as_float((ix & 0x007FFFFFu) | 0x3F000000u);   // [0.5, 1)
    float ef = (float)e;
    if (m < 0.707106781186547524f) { ef -= 1.0f; m = m + m; }      // exact
    float xm = m - 1.0f;                                           // exact
    float z = __fmul_rn(xm, xm);
    float y = 7.0376836292E-2f;
    y = __fmaf_rn(y, xm, -1.1514610310E-1f);
    y = __fmaf_rn(y, xm,  1.1676998740E-1f);
    y = __fmaf_rn(y, xm, -1.2420140846E-1f);
    y = __fmaf_rn(y, xm,  1.4249322787E-1f);
    y = __fmaf_rn(y, xm, -1.6668057665E-1f);
    y = __fmaf_rn(y, xm,  2.0000714765E-1f);
    y = __fmaf_rn(y, xm, -2.4999993993E-1f);
    y = __fmaf_rn(y, xm,  3.3333331174E-1f);
    y = __fmul_rn(y, xm);
    y = __fmul_rn(y, z);
    y = __fmaf_rn(ef, -2.12194440e-4f, y);
    y = __fmaf_rn(z, -0.5f, y);
    float r = __fadd_rn(xm, y);
    r = __fmaf_rn(ef, 0.693359375f, r);
    return r;
}
__device__ __forceinline__ float xla_expf(float x) {
    x = fminf(x, 88.723164f);
    x = fmaxf(x, -88.723164f);
    float m = floorf(__fmaf_rn(x, 1.44269504088896341f, 0.5f));
    float r = __fmaf_rn(m, -0.693359375f, x);
    r = __fmaf_rn(m, 2.12194440e-4f, r);
    float r2 = __fmul_rn(r, r);
    float p = 1.9875691500E-4f;
    p = __fmaf_rn(p, r, 1.3981999507E-3f);
    p = __fmaf_rn(p, r, 8.3334519073E-3f);
    p = __fmaf_rn(p, r, 4.1665795894E-2f);
    p = __fmaf_rn(p, r, 1.6666665459E-1f);
    p = __fmaf_rn(p, r, 5.0000001201E-1f);
    float y = __fmaf_rn(p, r2, r);
    y = __fadd_rn(y, 1.0f);
    int mi = (int)m;
    return __fmul_rn(y, __uint_as_float((unsigned int)(mi + 127) << 23));
}

// ---------------- binning math (bit-exact vs reference) ----------------
__device__ __forceinline__ void bin_of(float v, float hmin, float dh,
                                       bool& keep, int& idx, float& d) {
    keep = (v >= hmin) && (v <= 0.0f);
    float x  = __fdiv_rn(v - hmin, dh);
    float fi = floorf(x);
    idx = (int)fi;
    d   = x - fi;          // exact
}

// ---------------- kernel 0: reset min ----------------
__global__ void k_init() { g_min_ord = 0xFFFFFFFFu; }

// ---------------- kernel 1: global min of img0 ----------------
__global__ void k_min(const float* __restrict__ img, int n) {
    float m = 3.402823466e38f;
    int stride = gridDim.x * blockDim.x;
    for (int i = blockIdx.x * blockDim.x + threadIdx.x; i < n; i += stride)
        m = fminf(m, img[i]);
    #pragma unroll
    for (int o = 16; o; o >>= 1) m = fminf(m, __shfl_xor_sync(0xFFFFFFFFu, m, o));
    __shared__ float sm[32];
    int lane = threadIdx.x & 31, w = threadIdx.x >> 5;
    if (lane == 0) sm[w] = m;
    __syncthreads();
    if (w == 0) {
        int nw = (blockDim.x + 31) >> 5;
        m = (lane < nw) ? sm[lane] : 3.402823466e38f;
        #pragma unroll
        for (int o = 16; o; o >>= 1) m = fminf(m, __shfl_xor_sync(0xFFFFFFFFu, m, o));
        if (lane == 0) atomicMin(&g_min_ord, f2ord(m));
    }
}

// ---------------- kernel 2: per-(bin, chunk) counts (block per chunk) ----------
__global__ void k_count(const float* __restrict__ i0, const float* __restrict__ i1,
                        int n, int nchunk) {
    __shared__ unsigned int sc0[256], sc1[256];
    int t = threadIdx.x;
    sc0[t] = 0u; sc1[t] = 0u;
    __syncthreads();

    float hmin = ord2f(g_min_ord);
    float dh   = __fdiv_rn(0.0f - hmin, 255.0f);
    int chunk = blockIdx.x;
    int base  = chunk << CHUNK_LG;

    #pragma unroll
    for (int wv = 0; wv < (CHUNK / 256); wv++) {
        int i = base + (wv << 8) + t;
        if (i < n) {
            bool keep; int idx; float d;
            bin_of(i0[i], hmin, dh, keep, idx, d);
            if (keep) atomicAdd(&sc0[idx], 1u);
            bin_of(i1[i], hmin, dh, keep, idx, d);
            if (keep) atomicAdd(&sc1[idx], 1u);
        }
    }
    __syncthreads();
    g_cnt0[t * nchunk + chunk] = sc0[t];
    g_cnt1[t * nchunk + chunk] = sc1[t];
}

// ---------------- kernel 3: scan counts -> global start offsets ----------------
__global__ void k_scan(int nchunk) {
    int img = threadIdx.x >> 8;
    int b   = threadIdx.x & 255;
    unsigned int* cnt = img ? g_cnt1 : g_cnt0;
    unsigned int* bs  = img ? g_bs1  : g_bs0;

    unsigned int tot = 0;
    for (int c = 0; c < nchunk; c++) tot += cnt[b * nchunk + c];

    __shared__ unsigned int s_tot[512];
    s_tot[threadIdx.x] = tot;
    __syncthreads();
    if (b == 0) {
        unsigned int run = 0;
        for (int j = 0; j < 256; j++) {
            unsigned int v = s_tot[(img << 8) + j];
            s_tot[(img << 8) + j] = run;
            run += v;
        }
        bs[256] = run;
    }
    __syncthreads();
    unsigned int run = s_tot[threadIdx.x];
    bs[b] = run;
    for (int c = 0; c < nchunk; c++) {
        unsigned int v = cnt[b * nchunk + c];
        cnt[b * nchunk + c] = run;
        run += v;
    }
}

// ---------------- kernel 4: stable placement, parallel ranking ----------------
// grid (nchunk, 2), 256 threads. All ordering is tid-based => deterministic.
__global__ void k_place(const float* __restrict__ i0, const float* __restrict__ i1,
                        int n, int nchunk) {
    __shared__ unsigned int s_start[256];
    __shared__ __align__(16) unsigned short s_wc[256][8];   // per (bin, warp) counts

    int img = blockIdx.y;
    const float* in = img ? i1 : i0;
    const unsigned int* cnt = img ? g_cnt1 : g_cnt0;
    float* outp = img ? g_sorted1 : g_sorted0;

    int chunk = blockIdx.x;
    int base  = chunk << CHUNK_LG;
    int t     = threadIdx.x;
    int lane  = t & 31, w = t >> 5;

    s_start[t] = cnt[t * nchunk + chunk];
    *(uint4*)&s_wc[t][0] = make_uint4(0u, 0u, 0u, 0u);
    float hmin = ord2f(g_min_ord);
    float dh   = __fdiv_rn(0.0f - hmin, 255.0f);
    __syncthreads();

    #pragma unroll 1
    for (int wv = 0; wv < (CHUNK / 256); wv++) {
        int i = base + (wv << 8) + t;
        float v = (i < n) ? in[i] : 1.0f;
        bool keep; int idx; float d;
        bin_of(v, hmin, dh, keep, idx, d);
        if (i >= n) keep = false;

        unsigned int key = keep ? (unsigned int)idx : (0x1000u + (unsigned int)t);
        unsigned int mask = __match_any_sync(0xFFFFFFFFu, key);
        int rank = __popc(mask & ((1u << lane) - 1u));
        if (keep && rank == 0) s_wc[idx][w] = (unsigned short)__popc(mask);
        __syncthreads();

        if (keep) {
            unsigned int off = s_start[idx] + (unsigned int)rank;
            for (int w2 = 0; w2 < w; w2++) off += (unsigned int)s_wc[idx][w2];
            outp[off] = d;
        }
        __syncthreads();

        // thread t owns bin t: advance start, clear counts
        uint4 packed = *(uint4*)&s_wc[t][0];
        const unsigned short* wc = (const unsigned short*)&packed;
        unsigned int tot = 0;
        #pragma unroll
        for (int k = 0; k < 8; k++) tot += wc[k];
        if (tot) {
            s_start[t] += tot;
            *(uint4*)&s_wc[t][0] = make_uint4(0u, 0u, 0u, 0u);
        }
        __syncthreads();
    }
}

// ---------------- kernel 5: exact sequential f32 fold, staged through smem -----
// grid (256, 2), 160 threads: warp 0 lane 0 folds; warps 1..4 (128 threads)
// stage double-buffered tiles. Chain: group b with (1-d), then group b-1 with d.
__global__ void k_fold() {
    __shared__ float buf[2][FT];
    int img = blockIdx.y;
    const float* __restrict__ sd = img ? g_sorted1 : g_sorted0;
    const unsigned int* bs = img ? g_bs1 : g_bs0;
    float* h = img ? g_h1 : g_h0;
    int b = blockIdx.x;
    int t = threadIdx.x;

    unsigned int sA = bs[b], eA = bs[b + 1];
    unsigned int nA = eA - sA;
    unsigned int sB = (b > 0) ? bs[b - 1] : 0u;
    unsigned int nB = (b > 0) ? (bs[b] - sB) : 0u;
    unsigned int total = nA + nB;
    int ntile = (int)((total + FT - 1) / FT);

    // stage tile 0 (loader threads: t in [32,160))
    if (t >= 32) {
        int L = t - 32;
        unsigned int lim = (total < (unsigned int)FT) ? total : (unsigned int)FT;
        for (unsigned int j = (unsigned int)L; j < lim; j += 128u)
            buf[0][j] = (j < nA) ? sd[sA + j] : sd[sB + (j - nA)];
    }
    __syncthreads();

    float acc = 0.0f;
    for (int k = 0; k < ntile; k++) {
        int cur = k & 1;
        if (t >= 32) {
            if (k + 1 < ntile) {                     // prefetch next tile
                unsigned int nb = (unsigned int)(k + 1) * FT;
                unsigned int rem = total - nb;
                unsigned int lim = (rem < (unsigned int)FT) ? rem : (unsigned int)FT;
                int L = t - 32;
                for (unsigned int j = (unsigned int)L; j < lim; j += 128u) {
                    unsigned int jj = nb + j;
                    buf[cur ^ 1][j] = (jj < nA) ? sd[sA + jj] : sd[sB + (jj - nA)];
                }
            }
        } else if (t == 0) {                         // fold current tile
            unsigned int tb = (unsigned int)k * FT;
            unsigned int rem = total - tb;
            unsigned int m = (rem < (unsigned int)FT) ? rem : (unsigned int)FT;
            unsigned int mA = (tb < nA) ? ((nA - tb < m) ? (nA - tb) : m) : 0u;
            const float* B = buf[cur];
            unsigned int i = 0;
            #pragma unroll 8
            for (; i < mA; i++) acc = __fadd_rn(acc, __fsub_rn(1.0f, B[i]));
            #pragma unroll 8
            for (; i < m; i++)  acc = __fadd_rn(acc, B[i]);
        }
        __syncthreads();
    }
    if (t == 0) h[b] = acc;
}

// ---------------- kernel 6: finalize (single thread, reference op-order) -------
__global__ void k_final(float* __restrict__ out) {
    if (threadIdx.x != 0 || blockIdx.x != 0) return;

    float S0 = 0.0f, S1 = 0.0f;
    for (int t = 0; t < NBIN; t++) S0 = __fadd_rn(S0, g_h0[t]);
    for (int t = 0; t < NBIN; t++) S1 = __fadd_rn(S1, g_h1[t]);

    float d0 = __fadd_rn(S0, EPSF);
    float d1 = __fadd_rn(S1, EPSF);

    float acc = 0.0f;
    for (int t = 0; t < NBIN; t++) {
        float h0n = __fdiv_rn(__fadd_rn(g_h0[t], EPSF), d0);
        float h1n = __fdiv_rn(__fadd_rn(g_h1[t], EPSF), d1);
        float num = __fadd_rn(h1n, EPSF);
        float qi  = __fdiv_rn(num, h1n);
        float qt  = __fdiv_rn(num, h0n);
        float inp = xla_logf(qi);
        float tgt = xla_logf(qt);
        float et  = xla_expf(tgt);
        float term = __fmul_rn(et, __fsub_rn(tgt, inp));
        acc = __fadd_rn(acc, term);
    }
    out[0] = __fdiv_rn(acc, 256.0f);
}

// ---------------- launch ----------------
extern "C" void kernel_launch(void* const* d_in, const int* in_sizes, int n_in,
                              void* d_out, int out_size) {
    const float* img0 = (const float*)d_in[0];
    const float* img1 = (const float*)d_in[1];
    float* out = (float*)d_out;
    int n = in_sizes[0];
    if (n > MAXN) n = MAXN;
    int nchunk = (n + CHUNK - 1) / CHUNK;

    k_init <<<1, 1>>>();
    k_min  <<<1184, 256>>>(img0, n);
    k_count<<<nchunk, 256>>>(img0, img1, n, nchunk);
    k_scan <<<1, 512>>>(nchunk);
    k_place<<<dim3(nchunk, 2), 256>>>(img0, img1, n, nchunk);
    k_fold <<<dim3(256, 2), 160>>>();
    k_final<<<1, 32>>>(out);
}

// round 11
// speedup vs baseline: 4.4098x; 1.3791x over previous
#include <cuda_runtime.h>

#define NBIN 256
#define EPSF 1e-10f
#define CHUNK_LG 12
#define CHUNK (1 << CHUNK_LG)          // 4096 elements per chunk
#define MAXN 67108864                  // 4*256^3
#define MAXCHUNK (MAXN / CHUNK)        // 16384
#define FT 4096                        // fold tile (floats)

// ---------------- device scratch (static; no runtime allocation) ----------------
__device__ unsigned int g_min_ord;
__device__ unsigned int g_cnt0[256 * MAXCHUNK];   // [bin*nchunk + chunk]
__device__ unsigned int g_cnt1[256 * MAXCHUNK];
__device__ unsigned int g_bs0[NBIN + 1];          // global group starts
__device__ unsigned int g_bs1[NBIN + 1];
__device__ float g_sorted0[MAXN];                 // d values, stably sorted by bin
__device__ float g_sorted1[MAXN];
__device__ float g_h0[NBIN];
__device__ float g_h1[NBIN];

// Order-preserving float<->uint so unsigned atomicMin == float min.
__device__ __forceinline__ unsigned int f2ord(float f) {
    unsigned int u = __float_as_uint(f);
    return (u & 0x80000000u) ? ~u : (u | 0x80000000u);
}
__device__ __forceinline__ float ord2f(unsigned int o) {
    return __uint_as_float((o & 0x80000000u) ? (o & 0x7FFFFFFFu) : ~o);
}

// ---------------- Cephes-style f32 log/exp (XLA:CPU lineage, FMA form) ----------
__device__ __forceinline__ float xla_logf(float x) {
    unsigned int ix = __float_as_uint(x);
    int e = (int)(ix >> 23) - 126;
    float m = __uint_as_float((ix & 0x007FFFFFu) | 0x3F000000u);   // [0.5, 1)
    float ef = (float)e;
    if (m < 0.707106781186547524f) { ef -= 1.0f; m = m + m; }      // exact
    float xm = m - 1.0f;                                           // exact
    float z = __fmul_rn(xm, xm);
    float y = 7.0376836292E-2f;
    y = __fmaf_rn(y, xm, -1.1514610310E-1f);
    y = __fmaf_rn(y, xm,  1.1676998740E-1f);
    y = __fmaf_rn(y, xm, -1.2420140846E-1f);
    y = __fmaf_rn(y, xm,  1.4249322787E-1f);
    y = __fmaf_rn(y, xm, -1.6668057665E-1f);
    y = __fmaf_rn(y, xm,  2.0000714765E-1f);
    y = __fmaf_rn(y, xm, -2.4999993993E-1f);
    y = __fmaf_rn(y, xm,  3.3333331174E-1f);
    y = __fmul_rn(y, xm);
    y = __fmul_rn(y, z);
    y = __fmaf_rn(ef, -2.12194440e-4f, y);
    y = __fmaf_rn(z, -0.5f, y);
    float r = __fadd_rn(xm, y);
    r = __fmaf_rn(ef, 0.693359375f, r);
    return r;
}
__device__ __forceinline__ float xla_expf(float x) {
    x = fminf(x, 88.723164f);
    x = fmaxf(x, -88.723164f);
    float m = floorf(__fmaf_rn(x, 1.44269504088896341f, 0.5f));
    float r = __fmaf_rn(m, -0.693359375f, x);
    r = __fmaf_rn(m, 2.12194440e-4f, r);
    float r2 = __fmul_rn(r, r);
    float p = 1.9875691500E-4f;
    p = __fmaf_rn(p, r, 1.3981999507E-3f);
    p = __fmaf_rn(p, r, 8.3334519073E-3f);
    p = __fmaf_rn(p, r, 4.1665795894E-2f);
    p = __fmaf_rn(p, r, 1.6666665459E-1f);
    p = __fmaf_rn(p, r, 5.0000001201E-1f);
    float y = __fmaf_rn(p, r2, r);
    y = __fadd_rn(y, 1.0f);
    int mi = (int)m;
    return __fmul_rn(y, __uint_as_float((unsigned int)(mi + 127) << 23));
}

// ---------------- binning math (bit-exact vs reference) ----------------
__device__ __forceinline__ void bin_of(float v, float hmin, float dh,
                                       bool& keep, int& idx, float& d) {
    keep = (v >= hmin) && (v <= 0.0f);
    float x  = __fdiv_rn(v - hmin, dh);
    float fi = floorf(x);
    idx = (int)fi;
    d   = x - fi;          // exact
}

// ---------------- kernel 0: reset min ----------------
__global__ void k_init() { g_min_ord = 0xFFFFFFFFu; }

// ---------------- kernel 1: global min of img0 ----------------
__global__ void k_min(const float* __restrict__ img, int n) {
    float m = 3.402823466e38f;
    int stride = gridDim.x * blockDim.x;
    for (int i = blockIdx.x * blockDim.x + threadIdx.x; i < n; i += stride)
        m = fminf(m, img[i]);
    #pragma unroll
    for (int o = 16; o; o >>= 1) m = fminf(m, __shfl_xor_sync(0xFFFFFFFFu, m, o));
    __shared__ float sm[32];
    int lane = threadIdx.x & 31, w = threadIdx.x >> 5;
    if (lane == 0) sm[w] = m;
    __syncthreads();
    if (w == 0) {
        int nw = (blockDim.x + 31) >> 5;
        m = (lane < nw) ? sm[lane] : 3.402823466e38f;
        #pragma unroll
        for (int o = 16; o; o >>= 1) m = fminf(m, __shfl_xor_sync(0xFFFFFFFFu, m, o));
        if (lane == 0) atomicMin(&g_min_ord, f2ord(m));
    }
}

// ---------------- kernel 2: per-(bin, chunk) counts (block per chunk) ----------
__global__ void k_count(const float* __restrict__ i0, const float* __restrict__ i1,
                        int n, int nchunk) {
    __shared__ unsigned int sc0[256], sc1[256];
    int t = threadIdx.x;
    sc0[t] = 0u; sc1[t] = 0u;
    __syncthreads();

    float hmin = ord2f(g_min_ord);
    float dh   = __fdiv_rn(0.0f - hmin, 255.0f);
    int chunk = blockIdx.x;
    int base  = chunk << CHUNK_LG;

    #pragma unroll
    for (int wv = 0; wv < (CHUNK / 256); wv++) {
        int i = base + (wv << 8) + t;
        if (i < n) {
            bool keep; int idx; float d;
            bin_of(i0[i], hmin, dh, keep, idx, d);
            if (keep) atomicAdd(&sc0[idx], 1u);
            bin_of(i1[i], hmin, dh, keep, idx, d);
            if (keep) atomicAdd(&sc1[idx], 1u);
        }
    }
    __syncthreads();
    g_cnt0[t * nchunk + chunk] = sc0[t];
    g_cnt1[t * nchunk + chunk] = sc1[t];
}

// ---------------- kernel 3: scan counts -> global start offsets ----------------
__global__ void k_scan(int nchunk) {
    int img = threadIdx.x >> 8;
    int b   = threadIdx.x & 255;
    unsigned int* cnt = img ? g_cnt1 : g_cnt0;
    unsigned int* bs  = img ? g_bs1  : g_bs0;

    unsigned int tot = 0;
    for (int c = 0; c < nchunk; c++) tot += cnt[b * nchunk + c];

    __shared__ unsigned int s_tot[512];
    s_tot[threadIdx.x] = tot;
    __syncthreads();
    if (b == 0) {
        unsigned int run = 0;
        for (int j = 0; j < 256; j++) {
            unsigned int v = s_tot[(img << 8) + j];
            s_tot[(img << 8) + j] = run;
            run += v;
        }
        bs[256] = run;
    }
    __syncthreads();
    unsigned int run = s_tot[threadIdx.x];
    bs[b] = run;
    for (int c = 0; c < nchunk; c++) {
        unsigned int v = cnt[b * nchunk + c];
        cnt[b * nchunk + c] = run;
        run += v;
    }
}

// ---------------- kernel 4: stable placement, parallel ranking ----------------
// grid (nchunk, 2), 256 threads. All ordering is tid-based => deterministic.
__global__ void k_place(const float* __restrict__ i0, const float* __restrict__ i1,
                        int n, int nchunk) {
    __shared__ unsigned int s_start[256];
    __shared__ __align__(16) unsigned short s_wc[256][8];   // per (bin, warp) counts

    int img = blockIdx.y;
    const float* in = img ? i1 : i0;
    const unsigned int* cnt = img ? g_cnt1 : g_cnt0;
    float* outp = img ? g_sorted1 : g_sorted0;

    int chunk = blockIdx.x;
    int base  = chunk << CHUNK_LG;
    int t     = threadIdx.x;
    int lane  = t & 31, w = t >> 5;

    s_start[t] = cnt[t * nchunk + chunk];
    *(uint4*)&s_wc[t][0] = make_uint4(0u, 0u, 0u, 0u);
    float hmin = ord2f(g_min_ord);
    float dh   = __fdiv_rn(0.0f - hmin, 255.0f);
    __syncthreads();

    #pragma unroll 1
    for (int wv = 0; wv < (CHUNK / 256); wv++) {
        int i = base + (wv << 8) + t;
        float v = (i < n) ? in[i] : 1.0f;
        bool keep; int idx; float d;
        bin_of(v, hmin, dh, keep, idx, d);
        if (i >= n) keep = false;

        unsigned int key = keep ? (unsigned int)idx : (0x1000u + (unsigned int)t);
        unsigned int mask = __match_any_sync(0xFFFFFFFFu, key);
        int rank = __popc(mask & ((1u << lane) - 1u));
        if (keep && rank == 0) s_wc[idx][w] = (unsigned short)__popc(mask);
        __syncthreads();

        if (keep) {
            unsigned int off = s_start[idx] + (unsigned int)rank;
            for (int w2 = 0; w2 < w; w2++) off += (unsigned int)s_wc[idx][w2];
            outp[off] = d;
        }
        __syncthreads();

        // thread t owns bin t: advance start, clear counts
        uint4 packed = *(uint4*)&s_wc[t][0];
        const unsigned short* wc = (const unsigned short*)&packed;
        unsigned int tot = 0;
        #pragma unroll
        for (int k = 0; k < 8; k++) tot += wc[k];
        if (tot) {
            s_start[t] += tot;
            *(uint4*)&s_wc[t][0] = make_uint4(0u, 0u, 0u, 0u);
        }
        __syncthreads();
    }
}

// ---------------- kernel 5: exact sequential f32 fold, staged through smem -----
// grid (256, 2), 160 threads. Loader warps (t in [32,160)) stage double-buffered
// 4096-float tiles and APPLY the weight transform: w=(1-d) for the group-b
// segment, w=d for the group-(b-1) segment (same __fsub_rn bits as before).
// Warp-0 lane-0 folds full tiles with a compile-time-sized float4 loop:
// 4xLDS.128 + 16 chained FADDs per 16 elements => ~4.1 cyc/elem. The chained
// __fadd_rn sequence is dependency-ordered; ptxas cannot reassociate it, so the
// result is bit-identical to the scalar fold.
__global__ void k_fold() {
    __shared__ __align__(16) float buf[2][FT];
    int img = blockIdx.y;
    const float* __restrict__ sd = img ? g_sorted1 : g_sorted0;
    const unsigned int* bs = img ? g_bs1 : g_bs0;
    float* h = img ? g_h1 : g_h0;
    int b = blockIdx.x;
    int t = threadIdx.x;

    unsigned int sA = bs[b], eA = bs[b + 1];
    unsigned int nA = eA - sA;                       // group b   -> weight (1-d)
    unsigned int sB = (b > 0) ? bs[b - 1] : 0u;
    unsigned int nB = (b > 0) ? (bs[b] - sB) : 0u;   // group b-1 -> weight d
    unsigned int total = nA + nB;
    int ntile = (int)((total + FT - 1) / FT);

    // stage tile 0
    if (t >= 32 && ntile > 0) {
        unsigned int lim = (total < (unsigned int)FT) ? total : (unsigned int)FT;
        for (unsigned int j = (unsigned int)(t - 32); j < lim; j += 128u)
            buf[0][j] = (j < nA) ? __fsub_rn(1.0f, sd[sA + j])
                                 : sd[sB + (j - nA)];
    }
    __syncthreads();

    float acc = 0.0f;
    for (int k = 0; k < ntile; k++) {
        int cur = k & 1;
        if (t >= 32) {
            if (k + 1 < ntile) {                     // prefetch next tile
                unsigned int nb = (unsigned int)(k + 1) * FT;
                unsigned int rem = total - nb;
                unsigned int lim = (rem < (unsigned int)FT) ? rem : (unsigned int)FT;
                for (unsigned int j = (unsigned int)(t - 32); j < lim; j += 128u) {
                    unsigned int jj = nb + j;
                    buf[cur ^ 1][j] = (jj < nA) ? __fsub_rn(1.0f, sd[sA + jj])
                                                : sd[sB + (jj - nA)];
                }
            }
        } else if (t == 0) {
            unsigned int rem = total - (unsigned int)k * FT;
            if (rem >= (unsigned int)FT) {
                // full tile: fixed trip count, vectorized, unrolled
                const float4* __restrict__ B4 = (const float4*)buf[cur];
                #pragma unroll 4
                for (int i = 0; i < FT / 4; i++) {
                    float4 v = B4[i];
                    acc = __fadd_rn(acc, v.x);
                    acc = __fadd_rn(acc, v.y);
                    acc = __fadd_rn(acc, v.z);
                    acc = __fadd_rn(acc, v.w);
                }
            } else {
                const float* __restrict__ B = buf[cur];
                for (unsigned int i = 0; i < rem; i++)
                    acc = __fadd_rn(acc, B[i]);
            }
        }
        __syncthreads();
    }
    if (t == 0) h[b] = acc;
}

// ---------------- kernel 6: finalize (single thread, reference op-order) -------
__global__ void k_final(float* __restrict__ out) {
    if (threadIdx.x != 0 || blockIdx.x != 0) return;

    float S0 = 0.0f, S1 = 0.0f;
    for (int t = 0; t < NBIN; t++) S0 = __fadd_rn(S0, g_h0[t]);
    for (int t = 0; t < NBIN; t++) S1 = __fadd_rn(S1, g_h1[t]);

    float d0 = __fadd_rn(S0, EPSF);
    float d1 = __fadd_rn(S1, EPSF);

    float acc = 0.0f;
    for (int t = 0; t < NBIN; t++) {
        float h0n = __fdiv_rn(__fadd_rn(g_h0[t], EPSF), d0);
        float h1n = __fdiv_rn(__fadd_rn(g_h1[t], EPSF), d1);
        float num = __fadd_rn(h1n, EPSF);
        float qi  = __fdiv_rn(num, h1n);
        float qt  = __fdiv_rn(num, h0n);
        float inp = xla_logf(qi);
        float tgt = xla_logf(qt);
        float et  = xla_expf(tgt);
        float term = __fmul_rn(et, __fsub_rn(tgt, inp));
        acc = __fadd_rn(acc, term);
    }
    out[0] = __fdiv_rn(acc, 256.0f);
}

// ---------------- launch ----------------
extern "C" void kernel_launch(void* const* d_in, const int* in_sizes, int n_in,
                              void* d_out, int out_size) {
    const float* img0 = (const float*)d_in[0];
    const float* img1 = (const float*)d_in[1];
    float* out = (float*)d_out;
    int n = in_sizes[0];
    if (n > MAXN) n = MAXN;
    int nchunk = (n + CHUNK - 1) / CHUNK;

    k_init <<<1, 1>>>();
    k_min  <<<1184, 256>>>(img0, n);
    k_count<<<nchunk, 256>>>(img0, img1, n, nchunk);
    k_scan <<<1, 512>>>(nchunk);
    k_place<<<dim3(nchunk, 2), 256>>>(img0, img1, n, nchunk);
    k_fold <<<dim3(256, 2), 160>>>();
    k_final<<<1, 32>>>(out);
}